// round 13
// baseline (speedup 1.0000x reference)
#include <cuda_runtime.h>
#include <math.h>
#include <stdint.h>

// Problem constants
#define B_    2
#define T_    2048
#define H_    1024
#define NH_   16
#define HD_   64
#define WIN_  256

// Scratch (device globals — allocation-free per harness rules)
__device__ float g_qkv[(size_t)B_ * T_ * 3 * H_];    // [B,T,3H]
__device__ float g_att[(size_t)B_ * T_ * H_];        // attn out, normal layout
__device__ float g_xp[(size_t)B_ * T_ * H_];         // x, fragment-permuted
__device__ float g_attp[(size_t)B_ * T_ * H_];       // attn out, fragment-permuted
__device__ float g_wqkvp[(size_t)H_ * 3 * H_];       // W_qkv, fragment-permuted
__device__ float g_woutp[(size_t)H_ * H_];           // W_out, fragment-permuted

__device__ __forceinline__ float f2tf32(float x) {
    uint32_t u;
    asm("cvt.rna.tf32.f32 %0, %1;" : "=r"(u) : "f"(x));
    return __uint_as_float(u);
}

__device__ __forceinline__ void mma_tf32(float c[4], const uint32_t a[4], const uint32_t b[2]) {
    asm volatile(
        "mma.sync.aligned.m16n8k8.row.col.f32.tf32.tf32.f32 "
        "{%0,%1,%2,%3}, {%4,%5,%6,%7}, {%8,%9}, {%0,%1,%2,%3};"
        : "+f"(c[0]), "+f"(c[1]), "+f"(c[2]), "+f"(c[3])
        : "r"(a[0]), "r"(a[1]), "r"(a[2]), "r"(a[3]), "r"(b[0]), "r"(b[1]));
}

__device__ __forceinline__ void cp_async16(void* smem_dst, const void* gsrc) {
    uint32_t s = (uint32_t)__cvta_generic_to_shared(smem_dst);
    asm volatile("cp.async.cg.shared.global [%0], [%1], 16;" :: "r"(s), "l"(gsrc));
}
__device__ __forceinline__ void cp_commit() {
    asm volatile("cp.async.commit_group;");
}
template <int N>
__device__ __forceinline__ void cp_wait() {
    asm volatile("cp.async.wait_group %0;" :: "n"(N));
}

// ---------------------------------------------------------------------------
// Repack A: src [M][K] row-major fp32 -> dst fragment-permuted + tf32-rounded.
// dst 16B chunk idx = (mt*(K/8) + kt)*32 + lane, holds that thread's
// m16n8k8 tf32 A fragment for tile (mt, kt).
// ---------------------------------------------------------------------------
__global__ void repack_a_kernel(const float* __restrict__ src,
                                float* __restrict__ dst, int M, int K)
{
    const int idx = blockIdx.x * blockDim.x + threadIdx.x;
    const int total = (M >> 4) * (K >> 3) * 32;
    if (idx >= total) return;
    const int lane = idx & 31;
    const int kt   = (idx >> 5) % (K >> 3);
    const int mt   = idx / (32 * (K >> 3));
    const int grp = lane >> 2, qid = lane & 3;
    const int r0 = mt * 16 + grp, c0 = kt * 8 + qid;
    float4 v;
    v.x = f2tf32(src[(size_t)r0 * K + c0]);
    v.y = f2tf32(src[(size_t)(r0 + 8) * K + c0]);
    v.z = f2tf32(src[(size_t)r0 * K + c0 + 4]);
    v.w = f2tf32(src[(size_t)(r0 + 8) * K + c0 + 4]);
    ((float4*)dst)[idx] = v;
}

// ---------------------------------------------------------------------------
// Repack B: src [K][N] row-major fp32 -> fragment-permuted + tf32-rounded.
// dst 16B chunk idx = (nt*(K/16) + kp)*32 + lane; elements 0,1 = B fragment
// for ks=2kp; elements 2,3 = ks=2kp+1.
// ---------------------------------------------------------------------------
__global__ void repack_b_kernel(const float* __restrict__ src,
                                float* __restrict__ dst, int K, int N)
{
    const int idx = blockIdx.x * blockDim.x + threadIdx.x;
    const int total = (N >> 3) * (K >> 4) * 32;
    if (idx >= total) return;
    const int lane = idx & 31;
    const int kp   = (idx >> 5) % (K >> 4);
    const int nt   = idx / (32 * (K >> 4));
    const int grp = lane >> 2, qid = lane & 3;
    const int c = nt * 8 + grp, r = kp * 16;
    float4 v;
    v.x = f2tf32(src[(size_t)(r + qid     ) * N + c]);
    v.y = f2tf32(src[(size_t)(r + qid +  4) * N + c]);
    v.z = f2tf32(src[(size_t)(r + qid +  8) * N + c]);
    v.w = f2tf32(src[(size_t)(r + qid + 12) * N + c]);
    ((float4*)dst)[idx] = v;
}

// ---------------------------------------------------------------------------
// TF32 tensor-core GEMM on fragment-permuted operands.
// CTA 128x256, 512 threads = 16 warps (4x4), warp tile 32x64, BK=32,
// 3-stage cp.async pipeline, one __syncthreads per chunk.
// All fragment loads are LDS.128. C[M,N] = A[M,K] @ B[K,N] + bias[N].
// ---------------------------------------------------------------------------
#define BM 128
#define BN 256
#define BK 32
#define NSTAGE 3
#define A_STAGE_BYTES (8 * 4 * 32 * 16)     // [mloc 8][ktloc 4][lane 32] x16B = 16384
#define B_STAGE_BYTES (32 * 2 * 32 * 16)    // [ntloc 32][kploc 2][lane 32] x16B = 32768
#define STAGE_BYTES   (A_STAGE_BYTES + B_STAGE_BYTES)   // 49152
#define GEMM_SMEM     (NSTAGE * STAGE_BYTES)            // 147456

__global__ __launch_bounds__(512, 1)
void gemm_tf32_bias(const float* __restrict__ Ap, const float* __restrict__ Bp,
                    const float* __restrict__ bias, float* __restrict__ C,
                    int M, int N, int K)
{
    extern __shared__ char smem[];

    const int tid  = threadIdx.x;
    const int wid  = tid >> 5;
    const int lane = tid & 31;
    const int wm   = wid >> 2;          // 0..3 (M dir, 32 rows each)
    const int wn   = wid & 3;           // 0..3 (N dir, 64 cols each)
    const int grp  = lane >> 2;
    const int qid  = lane & 3;
    const int bx = blockIdx.x, by = blockIdx.y;

    const int KT = K >> 3;              // k8-tiles
    const int KP = K >> 4;              // k16-pairs

    float acc[2][8][4];
#pragma unroll
    for (int m = 0; m < 2; m++)
#pragma unroll
        for (int n = 0; n < 8; n++)
#pragma unroll
            for (int r = 0; r < 4; r++) acc[m][n][r] = 0.f;

    const int NCH = K / BK;   // 32

    auto load_stage = [&](int it, int s) {
        char* As = smem + s * STAGE_BYTES;
        char* Bs = As + A_STAGE_BYTES;
        // A: 1024 x 16B chunks, layout [mloc(8)][ktloc(4)][lane(32)]
#pragma unroll
        for (int i = 0; i < 2; i++) {
            const int f = tid + i * 512;
            const int mloc = f >> 7;
            const int rest = f & 127;       // ktloc*32 + lane
            const size_t srcidx = ((size_t)(by * 8 + mloc) * KT + it * 4) * 32 + rest;
            cp_async16(As + f * 16, Ap + srcidx * 4);
        }
        // B: 2048 x 16B chunks, layout [ntloc(32)][kploc(2)][lane(32)]
#pragma unroll
        for (int i = 0; i < 4; i++) {
            const int f = tid + i * 512;
            const int ntloc = f >> 6;
            const int rest = f & 63;        // kploc*32 + lane
            const size_t srcidx = ((size_t)(bx * 32 + ntloc) * KP + it * 2) * 32 + rest;
            cp_async16(Bs + f * 16, Bp + srcidx * 4);
        }
        cp_commit();
    };

    load_stage(0, 0);
    load_stage(1, 1);

    int stage = 0;
    for (int it = 0; it < NCH; it++) {
        if (it + 1 < NCH) cp_wait<1>(); else cp_wait<0>();
        __syncthreads();

        if (it + 2 < NCH) {
            int s2 = stage + 2; if (s2 >= NSTAGE) s2 -= NSTAGE;
            load_stage(it + 2, s2);
        }

        const char* As = smem + stage * STAGE_BYTES;
        const char* Bs = As + A_STAGE_BYTES;

#pragma unroll
        for (int kp = 0; kp < 2; kp++) {
            uint4 bfrag[8];
#pragma unroll
            for (int n = 0; n < 8; n++)
                bfrag[n] = *(const uint4*)(Bs + ((((wn * 8 + n) * 2 + kp) * 32 + lane) << 4));
#pragma unroll
            for (int half = 0; half < 2; half++) {
                uint4 afrag[2];
#pragma unroll
                for (int m = 0; m < 2; m++)
                    afrag[m] = *(const uint4*)(As + ((((wm * 2 + m) * 4 + kp * 2 + half) * 32 + lane) << 4));
#pragma unroll
                for (int m = 0; m < 2; m++) {
                    const uint32_t a[4] = {afrag[m].x, afrag[m].y, afrag[m].z, afrag[m].w};
#pragma unroll
                    for (int n = 0; n < 8; n++) {
                        const uint32_t b[2] = {half ? bfrag[n].z : bfrag[n].x,
                                               half ? bfrag[n].w : bfrag[n].y};
                        mma_tf32(acc[m][n], a, b);
                    }
                }
            }
        }

        stage = stage + 1; if (stage >= NSTAGE) stage -= NSTAGE;
    }

    // Epilogue with bias (normal row-major C)
#pragma unroll
    for (int m = 0; m < 2; m++) {
        const int row0 = by * BM + wm * 32 + m * 16 + grp;
#pragma unroll
        for (int n = 0; n < 8; n++) {
            const int col = bx * BN + wn * 64 + n * 8 + qid * 2;
            const float b0 = bias[col], b1 = bias[col + 1];
            float2 v0 = make_float2(acc[m][n][0] + b0, acc[m][n][1] + b1);
            float2 v1 = make_float2(acc[m][n][2] + b0, acc[m][n][3] + b1);
            *(float2*)(C + (size_t)row0 * N + col)       = v0;
            *(float2*)(C + (size_t)(row0 + 8) * N + col) = v1;
        }
    }
}

// ---------------------------------------------------------------------------
// Banded causal attention on tensor cores (tf32 mma, flash online softmax).
// Unchanged (passing, ~58us). Writes g_att in normal layout, tf32-rounded.
// ---------------------------------------------------------------------------
#define ATTN_SMEM2 ((64*68*3 + 64*72) * 4)

__global__ __launch_bounds__(128)
void attn_mma_kernel(float* __restrict__ out)
{
    extern __shared__ float sm[];
    float* Qs = sm;                   // [64][68]
    float* Ps = Qs + 64 * 68;         // [64][68]
    float* Ks = Ps + 64 * 68;         // [64][68]
    float* Vs = Ks + 64 * 68;         // [64][72]

    const int qt  = blockIdx.x;
    const int h   = blockIdx.y;
    const int b   = blockIdx.z;
    const int tid = threadIdx.x;
    const int wid  = tid >> 5;
    const int lane = tid & 31;
    const int g = lane >> 2;
    const int q = lane & 3;
    const int r0 = wid * 16;

    const size_t rs = 3 * H_;
    const size_t base_bt = (size_t)b * T_ * rs + (size_t)h * HD_;
    const size_t qbase = base_bt + (size_t)(qt * 64) * rs;

#pragma unroll
    for (int it = 0; it < 8; it++) {
        const int idx = tid + it * 128;
        const int i = idx >> 4, d4 = (idx & 15) << 2;
        float4 v = *(const float4*)&g_qkv[qbase + (size_t)i * rs + d4];
        float4 w;
        w.x = f2tf32(v.x * 0.125f);
        w.y = f2tf32(v.y * 0.125f);
        w.z = f2tf32(v.z * 0.125f);
        w.w = f2tf32(v.w * 0.125f);
        *(float4*)&Qs[i * 68 + d4] = w;
    }

    float oc[8][4];
#pragma unroll
    for (int nt = 0; nt < 8; nt++)
#pragma unroll
        for (int r = 0; r < 4; r++) oc[nt][r] = 0.f;

    float m0 = -1e30f, m1 = -1e30f, l0 = 0.f, l1 = 0.f;

    int kt0 = qt - 4; if (kt0 < 0) kt0 = 0;

    for (int kt = kt0; kt <= qt; kt++) {
        __syncthreads();

        const size_t kbase = base_bt + (size_t)(kt * 64) * rs + H_;
#pragma unroll
        for (int it = 0; it < 8; it++) {
            const int idx = tid + it * 128;
            const int j = idx >> 4, d4 = (idx & 15) << 2;
            float4 kv = *(const float4*)&g_qkv[kbase + (size_t)j * rs + d4];
            float4 vv = *(const float4*)&g_qkv[kbase + H_ + (size_t)j * rs + d4];
            float4 kw, vw;
            kw.x = f2tf32(kv.x); kw.y = f2tf32(kv.y); kw.z = f2tf32(kv.z); kw.w = f2tf32(kv.w);
            vw.x = f2tf32(vv.x); vw.y = f2tf32(vv.y); vw.z = f2tf32(vv.z); vw.w = f2tf32(vv.w);
            *(float4*)&Ks[j * 68 + d4] = kw;
            *(float4*)&Vs[j * 72 + d4] = vw;
        }
        __syncthreads();

        float s[8][4];
#pragma unroll
        for (int nt = 0; nt < 8; nt++)
#pragma unroll
            for (int r = 0; r < 4; r++) s[nt][r] = 0.f;

#pragma unroll
        for (int ks = 0; ks < 8; ks++) {
            const int kb = ks * 8;
            uint32_t a[4];
            a[0] = __float_as_uint(Qs[(r0 + g    ) * 68 + kb + q    ]);
            a[1] = __float_as_uint(Qs[(r0 + g + 8) * 68 + kb + q    ]);
            a[2] = __float_as_uint(Qs[(r0 + g    ) * 68 + kb + q + 4]);
            a[3] = __float_as_uint(Qs[(r0 + g + 8) * 68 + kb + q + 4]);
#pragma unroll
            for (int nt = 0; nt < 8; nt++) {
                uint32_t bb[2];
                bb[0] = __float_as_uint(Ks[(nt * 8 + g) * 68 + kb + q    ]);
                bb[1] = __float_as_uint(Ks[(nt * 8 + g) * 68 + kb + q + 4]);
                mma_tf32(s[nt], a, bb);
            }
        }

        const int ig0 = qt * 64 + r0 + g;
        const int ig1 = ig0 + 8;
#pragma unroll
        for (int nt = 0; nt < 8; nt++) {
            const int jg = kt * 64 + nt * 8 + 2 * q;
            int d00 = ig0 - jg;     if (d00 < 0 || d00 >= WIN_) s[nt][0] = -1e30f;
            int d01 = ig0 - jg - 1; if (d01 < 0 || d01 >= WIN_) s[nt][1] = -1e30f;
            int d10 = ig1 - jg;     if (d10 < 0 || d10 >= WIN_) s[nt][2] = -1e30f;
            int d11 = ig1 - jg - 1; if (d11 < 0 || d11 >= WIN_) s[nt][3] = -1e30f;
        }
        float mx0 = -1e30f, mx1 = -1e30f;
#pragma unroll
        for (int nt = 0; nt < 8; nt++) {
            mx0 = fmaxf(mx0, fmaxf(s[nt][0], s[nt][1]));
            mx1 = fmaxf(mx1, fmaxf(s[nt][2], s[nt][3]));
        }
        mx0 = fmaxf(mx0, __shfl_xor_sync(0xffffffffu, mx0, 1));
        mx0 = fmaxf(mx0, __shfl_xor_sync(0xffffffffu, mx0, 2));
        mx1 = fmaxf(mx1, __shfl_xor_sync(0xffffffffu, mx1, 1));
        mx1 = fmaxf(mx1, __shfl_xor_sync(0xffffffffu, mx1, 2));

        const float mn0 = fmaxf(m0, mx0), mn1 = fmaxf(m1, mx1);
        const float e0 = __expf(m0 - mn0), e1 = __expf(m1 - mn1);
        float rs0 = 0.f, rs1 = 0.f;
#pragma unroll
        for (int nt = 0; nt < 8; nt++) {
            const float p00 = __expf(s[nt][0] - mn0);
            const float p01 = __expf(s[nt][1] - mn0);
            const float p10 = __expf(s[nt][2] - mn1);
            const float p11 = __expf(s[nt][3] - mn1);
            rs0 += p00 + p01;
            rs1 += p10 + p11;
            float2 v0 = make_float2(f2tf32(p00), f2tf32(p01));
            float2 v1 = make_float2(f2tf32(p10), f2tf32(p11));
            *(float2*)&Ps[(r0 + g    ) * 68 + nt * 8 + 2 * q] = v0;
            *(float2*)&Ps[(r0 + g + 8) * 68 + nt * 8 + 2 * q] = v1;
        }
        rs0 += __shfl_xor_sync(0xffffffffu, rs0, 1);
        rs0 += __shfl_xor_sync(0xffffffffu, rs0, 2);
        rs1 += __shfl_xor_sync(0xffffffffu, rs1, 1);
        rs1 += __shfl_xor_sync(0xffffffffu, rs1, 2);

        l0 = l0 * e0 + rs0;  m0 = mn0;
        l1 = l1 * e1 + rs1;  m1 = mn1;

#pragma unroll
        for (int nt = 0; nt < 8; nt++) {
            oc[nt][0] *= e0; oc[nt][1] *= e0;
            oc[nt][2] *= e1; oc[nt][3] *= e1;
        }
        __syncthreads();

#pragma unroll
        for (int ks = 0; ks < 8; ks++) {
            const int kb = ks * 8;
            uint32_t a[4];
            a[0] = __float_as_uint(Ps[(r0 + g    ) * 68 + kb + q    ]);
            a[1] = __float_as_uint(Ps[(r0 + g + 8) * 68 + kb + q    ]);
            a[2] = __float_as_uint(Ps[(r0 + g    ) * 68 + kb + q + 4]);
            a[3] = __float_as_uint(Ps[(r0 + g + 8) * 68 + kb + q + 4]);
#pragma unroll
            for (int nt = 0; nt < 8; nt++) {
                uint32_t bb[2];
                bb[0] = __float_as_uint(Vs[(kb + q    ) * 72 + nt * 8 + g]);
                bb[1] = __float_as_uint(Vs[(kb + q + 4) * 72 + nt * 8 + g]);
                mma_tf32(oc[nt], a, bb);
            }
        }
    }

    const float inv0 = 1.f / l0, inv1 = 1.f / l1;
    const int row0g = qt * 64 + r0 + g;
#pragma unroll
    for (int nt = 0; nt < 8; nt++) {
        const int col = h * HD_ + nt * 8 + 2 * q;
        float2 v0 = make_float2(f2tf32(oc[nt][0] * inv0), f2tf32(oc[nt][1] * inv0));
        float2 v1 = make_float2(f2tf32(oc[nt][2] * inv1), f2tf32(oc[nt][3] * inv1));
        *(float2*)&out[(size_t)(b * T_ + row0g    ) * H_ + col] = v0;
        *(float2*)&out[(size_t)(b * T_ + row0g + 8) * H_ + col] = v1;
    }
}

// ---------------------------------------------------------------------------
// Launch: repack(x, W) -> QKV GEMM -> attention -> repack(att) -> out GEMM
// ---------------------------------------------------------------------------
extern "C" void kernel_launch(void* const* d_in, const int* in_sizes, int n_in,
                              void* d_out, int out_size)
{
    const float* x     = (const float*)d_in[0];
    const float* W_qkv = (const float*)d_in[1];
    const float* b_qkv = (const float*)d_in[2];
    const float* W_out = (const float*)d_in[3];
    const float* b_out = (const float*)d_in[4];
    float* out = (float*)d_out;

    float* qkv;  cudaGetSymbolAddress((void**)&qkv,  g_qkv);
    float* att;  cudaGetSymbolAddress((void**)&att,  g_att);
    float* xp;   cudaGetSymbolAddress((void**)&xp,   g_xp);
    float* attp; cudaGetSymbolAddress((void**)&attp, g_attp);
    float* wqp;  cudaGetSymbolAddress((void**)&wqp,  g_wqkvp);
    float* wop;  cudaGetSymbolAddress((void**)&wop,  g_woutp);

    const int M = B_ * T_;   // 4096

    // 0) repack + tf32-round operands into fragment order
    {
        const int na = (M / 16) * (H_ / 8) * 32;            // x
        repack_a_kernel<<<(na + 255) / 256, 256>>>(x, xp, M, H_);
        const int nbq = ((3 * H_) / 8) * (H_ / 16) * 32;    // W_qkv
        repack_b_kernel<<<(nbq + 255) / 256, 256>>>(W_qkv, wqp, H_, 3 * H_);
        const int nbo = (H_ / 8) * (H_ / 16) * 32;          // W_out
        repack_b_kernel<<<(nbo + 255) / 256, 256>>>(W_out, wop, H_, H_);
    }

    cudaFuncSetAttribute(gemm_tf32_bias,
                         cudaFuncAttributeMaxDynamicSharedMemorySize, GEMM_SMEM);

    // 1) QKV projection: [4096,1024] @ [1024,3072] + bias
    {
        dim3 grid((3 * H_) / BN, M / BM);     // (12, 32)
        gemm_tf32_bias<<<grid, 512, GEMM_SMEM>>>(xp, wqp, b_qkv, qkv, M, 3 * H_, H_);
    }

    // 2) Banded attention
    {
        cudaFuncSetAttribute(attn_mma_kernel,
                             cudaFuncAttributeMaxDynamicSharedMemorySize, ATTN_SMEM2);
        dim3 grid(T_ / 64, NH_, B_);
        attn_mma_kernel<<<grid, 128, ATTN_SMEM2>>>(att);
    }

    // 2.5) repack attention output for GEMM2 A operand
    {
        const int na = (M / 16) * (H_ / 8) * 32;
        repack_a_kernel<<<(na + 255) / 256, 256>>>(att, attp, M, H_);
    }

    // 3) Output projection: [4096,1024] @ [1024,1024] + bias
    {
        dim3 grid(H_ / BN, M / BM);           // (4, 32)
        gemm_tf32_bias<<<grid, 512, GEMM_SMEM>>>(attp, wop, b_out, out, M, H_, H_);
    }
}

// round 14
// speedup vs baseline: 1.1796x; 1.1796x over previous
#include <cuda_runtime.h>
#include <math.h>
#include <stdint.h>

// Problem constants
#define B_    2
#define T_    2048
#define H_    1024
#define NH_   16
#define HD_   64
#define WIN_  256

// Scratch (device globals — allocation-free per harness rules)
__device__ float g_qkv[(size_t)B_ * T_ * 3 * H_];    // [B,T,3H]
__device__ float g_att[(size_t)B_ * T_ * H_];        // attn out, normal layout
__device__ float g_xp[(size_t)B_ * T_ * H_];         // x, fragment-permuted
__device__ float g_attp[(size_t)B_ * T_ * H_];       // attn out, fragment-permuted
__device__ float g_wqkvp[(size_t)H_ * 3 * H_];       // W_qkv, fragment-permuted
__device__ float g_woutp[(size_t)H_ * H_];           // W_out, fragment-permuted

__device__ __forceinline__ float f2tf32(float x) {
    uint32_t u;
    asm("cvt.rna.tf32.f32 %0, %1;" : "=r"(u) : "f"(x));
    return __uint_as_float(u);
}

__device__ __forceinline__ void mma_tf32(float c[4], const uint32_t a[4], const uint32_t b[2]) {
    asm volatile(
        "mma.sync.aligned.m16n8k8.row.col.f32.tf32.tf32.f32 "
        "{%0,%1,%2,%3}, {%4,%5,%6,%7}, {%8,%9}, {%0,%1,%2,%3};"
        : "+f"(c[0]), "+f"(c[1]), "+f"(c[2]), "+f"(c[3])
        : "r"(a[0]), "r"(a[1]), "r"(a[2]), "r"(a[3]), "r"(b[0]), "r"(b[1]));
}

__device__ __forceinline__ void cp_async16(void* smem_dst, const void* gsrc) {
    uint32_t s = (uint32_t)__cvta_generic_to_shared(smem_dst);
    asm volatile("cp.async.cg.shared.global [%0], [%1], 16;" :: "r"(s), "l"(gsrc));
}
__device__ __forceinline__ void cp_commit() {
    asm volatile("cp.async.commit_group;");
}
template <int N>
__device__ __forceinline__ void cp_wait() {
    asm volatile("cp.async.wait_group %0;" :: "n"(N));
}

// ---------------------------------------------------------------------------
// Repack A: src [M][K] row-major fp32 -> dst fragment-permuted + tf32-rounded.
// dst 16B chunk idx = (mt*(K/8) + kt)*32 + lane, holds that thread's
// m16n8k8 tf32 A fragment for tile (mt, kt).
// ---------------------------------------------------------------------------
__global__ void repack_a_kernel(const float* __restrict__ src,
                                float* __restrict__ dst, int M, int K)
{
    const int idx = blockIdx.x * blockDim.x + threadIdx.x;
    const int total = (M >> 4) * (K >> 3) * 32;
    if (idx >= total) return;
    const int lane = idx & 31;
    const int kt   = (idx >> 5) % (K >> 3);
    const int mt   = idx / (32 * (K >> 3));
    const int grp = lane >> 2, qid = lane & 3;
    const int r0 = mt * 16 + grp, c0 = kt * 8 + qid;
    float4 v;
    v.x = f2tf32(src[(size_t)r0 * K + c0]);
    v.y = f2tf32(src[(size_t)(r0 + 8) * K + c0]);
    v.z = f2tf32(src[(size_t)r0 * K + c0 + 4]);
    v.w = f2tf32(src[(size_t)(r0 + 8) * K + c0 + 4]);
    ((float4*)dst)[idx] = v;
}

// ---------------------------------------------------------------------------
// Repack B: src [K][N] row-major fp32 -> fragment-permuted + tf32-rounded.
// dst 16B chunk idx = (nt*(K/16) + kp)*32 + lane; elements 0,1 = B fragment
// for ks=2kp; elements 2,3 = ks=2kp+1.
// ---------------------------------------------------------------------------
__global__ void repack_b_kernel(const float* __restrict__ src,
                                float* __restrict__ dst, int K, int N)
{
    const int idx = blockIdx.x * blockDim.x + threadIdx.x;
    const int total = (N >> 3) * (K >> 4) * 32;
    if (idx >= total) return;
    const int lane = idx & 31;
    const int kp   = (idx >> 5) % (K >> 4);
    const int nt   = idx / (32 * (K >> 4));
    const int grp = lane >> 2, qid = lane & 3;
    const int c = nt * 8 + grp, r = kp * 16;
    float4 v;
    v.x = f2tf32(src[(size_t)(r + qid     ) * N + c]);
    v.y = f2tf32(src[(size_t)(r + qid +  4) * N + c]);
    v.z = f2tf32(src[(size_t)(r + qid +  8) * N + c]);
    v.w = f2tf32(src[(size_t)(r + qid + 12) * N + c]);
    ((float4*)dst)[idx] = v;
}

// ---------------------------------------------------------------------------
// TF32 tensor-core GEMM on fragment-permuted operands.
// CTA 128x128, 128 threads = 4 warps (2x2), warp tile 64x64 (same as R12),
// BK=32, 3-stage cp.async pipeline. 2 CTAs/SM co-resident -> two independent
// barrier domains per SM hide each other's pipeline bubbles.
// All fragment loads are LDS.128. C[M,N] = A[M,K] @ B[K,N] + bias[N].
// ---------------------------------------------------------------------------
#define BM 128
#define BN 128
#define BK 32
#define NSTAGE 3
#define A_STAGE_BYTES (8 * 4 * 32 * 16)     // [mloc 8][ktloc 4][lane 32] x16B = 16384
#define B_STAGE_BYTES (16 * 2 * 32 * 16)    // [ntloc 16][kploc 2][lane 32] x16B = 16384
#define STAGE_BYTES   (A_STAGE_BYTES + B_STAGE_BYTES)   // 32768
#define GEMM_SMEM     (NSTAGE * STAGE_BYTES)            // 98304 (x2 CTAs = 192KB/SM)

__global__ __launch_bounds__(128, 2)
void gemm_tf32_bias(const float* __restrict__ Ap, const float* __restrict__ Bp,
                    const float* __restrict__ bias, float* __restrict__ C,
                    int M, int N, int K)
{
    extern __shared__ char smem[];

    const int tid  = threadIdx.x;
    const int wid  = tid >> 5;
    const int lane = tid & 31;
    const int wm   = wid >> 1;          // 0..1 (M dir, 64 rows each)
    const int wn   = wid & 1;           // 0..1 (N dir, 64 cols each)
    const int grp  = lane >> 2;
    const int qid  = lane & 3;
    const int bx = blockIdx.x, by = blockIdx.y;

    const int KT = K >> 3;              // k8-tiles
    const int KP = K >> 4;              // k16-pairs

    float acc[4][8][4];
#pragma unroll
    for (int m = 0; m < 4; m++)
#pragma unroll
        for (int n = 0; n < 8; n++)
#pragma unroll
            for (int r = 0; r < 4; r++) acc[m][n][r] = 0.f;

    const int NCH = K / BK;   // 32

    auto load_stage = [&](int it, int s) {
        char* As = smem + s * STAGE_BYTES;
        char* Bs = As + A_STAGE_BYTES;
        // A: 1024 x 16B chunks, layout [mloc(8)][ktloc(4)][lane(32)]
#pragma unroll
        for (int i = 0; i < 8; i++) {
            const int f = tid + i * 128;
            const int mloc = f >> 7;
            const int rest = f & 127;       // ktloc*32 + lane
            const size_t srcidx = ((size_t)(by * 8 + mloc) * KT + it * 4) * 32 + rest;
            cp_async16(As + f * 16, Ap + srcidx * 4);
        }
        // B: 1024 x 16B chunks, layout [ntloc(16)][kploc(2)][lane(32)]
#pragma unroll
        for (int i = 0; i < 8; i++) {
            const int f = tid + i * 128;
            const int ntloc = f >> 6;
            const int rest = f & 63;        // kploc*32 + lane
            const size_t srcidx = ((size_t)(bx * 16 + ntloc) * KP + it * 2) * 32 + rest;
            cp_async16(Bs + f * 16, Bp + srcidx * 4);
        }
        cp_commit();
    };

    load_stage(0, 0);
    load_stage(1, 1);

    int stage = 0;
    for (int it = 0; it < NCH; it++) {
        if (it + 1 < NCH) cp_wait<1>(); else cp_wait<0>();
        __syncthreads();

        if (it + 2 < NCH) {
            int s2 = stage + 2; if (s2 >= NSTAGE) s2 -= NSTAGE;
            load_stage(it + 2, s2);
        }

        const char* As = smem + stage * STAGE_BYTES;
        const char* Bs = As + A_STAGE_BYTES;

#pragma unroll
        for (int kp = 0; kp < 2; kp++) {
            uint4 bfrag[8];
#pragma unroll
            for (int n = 0; n < 8; n++)
                bfrag[n] = *(const uint4*)(Bs + ((((wn * 8 + n) * 2 + kp) * 32 + lane) << 4));
#pragma unroll
            for (int half = 0; half < 2; half++) {
                uint4 afrag[4];
#pragma unroll
                for (int m = 0; m < 4; m++)
                    afrag[m] = *(const uint4*)(As + ((((wm * 4 + m) * 4 + kp * 2 + half) * 32 + lane) << 4));
#pragma unroll
                for (int m = 0; m < 4; m++) {
                    const uint32_t a[4] = {afrag[m].x, afrag[m].y, afrag[m].z, afrag[m].w};
#pragma unroll
                    for (int n = 0; n < 8; n++) {
                        const uint32_t b[2] = {half ? bfrag[n].z : bfrag[n].x,
                                               half ? bfrag[n].w : bfrag[n].y};
                        mma_tf32(acc[m][n], a, b);
                    }
                }
            }
        }

        stage = stage + 1; if (stage >= NSTAGE) stage -= NSTAGE;
    }

    // Epilogue with bias (normal row-major C)
#pragma unroll
    for (int m = 0; m < 4; m++) {
        const int row0 = by * BM + wm * 64 + m * 16 + grp;
#pragma unroll
        for (int n = 0; n < 8; n++) {
            const int col = bx * BN + wn * 64 + n * 8 + qid * 2;
            const float b0 = bias[col], b1 = bias[col + 1];
            float2 v0 = make_float2(acc[m][n][0] + b0, acc[m][n][1] + b1);
            float2 v1 = make_float2(acc[m][n][2] + b0, acc[m][n][3] + b1);
            *(float2*)(C + (size_t)row0 * N + col)       = v0;
            *(float2*)(C + (size_t)(row0 + 8) * N + col) = v1;
        }
    }
}

// ---------------------------------------------------------------------------
// Banded causal attention on tensor cores (tf32 mma, flash online softmax).
// Unchanged (passing, ~58us). Writes g_att in normal layout, tf32-rounded.
// ---------------------------------------------------------------------------
#define ATTN_SMEM2 ((64*68*3 + 64*72) * 4)

__global__ __launch_bounds__(128)
void attn_mma_kernel(float* __restrict__ out)
{
    extern __shared__ float sm[];
    float* Qs = sm;                   // [64][68]
    float* Ps = Qs + 64 * 68;         // [64][68]
    float* Ks = Ps + 64 * 68;         // [64][68]
    float* Vs = Ks + 64 * 68;         // [64][72]

    const int qt  = blockIdx.x;
    const int h   = blockIdx.y;
    const int b   = blockIdx.z;
    const int tid = threadIdx.x;
    const int wid  = tid >> 5;
    const int lane = tid & 31;
    const int g = lane >> 2;
    const int q = lane & 3;
    const int r0 = wid * 16;

    const size_t rs = 3 * H_;
    const size_t base_bt = (size_t)b * T_ * rs + (size_t)h * HD_;
    const size_t qbase = base_bt + (size_t)(qt * 64) * rs;

#pragma unroll
    for (int it = 0; it < 8; it++) {
        const int idx = tid + it * 128;
        const int i = idx >> 4, d4 = (idx & 15) << 2;
        float4 v = *(const float4*)&g_qkv[qbase + (size_t)i * rs + d4];
        float4 w;
        w.x = f2tf32(v.x * 0.125f);
        w.y = f2tf32(v.y * 0.125f);
        w.z = f2tf32(v.z * 0.125f);
        w.w = f2tf32(v.w * 0.125f);
        *(float4*)&Qs[i * 68 + d4] = w;
    }

    float oc[8][4];
#pragma unroll
    for (int nt = 0; nt < 8; nt++)
#pragma unroll
        for (int r = 0; r < 4; r++) oc[nt][r] = 0.f;

    float m0 = -1e30f, m1 = -1e30f, l0 = 0.f, l1 = 0.f;

    int kt0 = qt - 4; if (kt0 < 0) kt0 = 0;

    for (int kt = kt0; kt <= qt; kt++) {
        __syncthreads();

        const size_t kbase = base_bt + (size_t)(kt * 64) * rs + H_;
#pragma unroll
        for (int it = 0; it < 8; it++) {
            const int idx = tid + it * 128;
            const int j = idx >> 4, d4 = (idx & 15) << 2;
            float4 kv = *(const float4*)&g_qkv[kbase + (size_t)j * rs + d4];
            float4 vv = *(const float4*)&g_qkv[kbase + H_ + (size_t)j * rs + d4];
            float4 kw, vw;
            kw.x = f2tf32(kv.x); kw.y = f2tf32(kv.y); kw.z = f2tf32(kv.z); kw.w = f2tf32(kv.w);
            vw.x = f2tf32(vv.x); vw.y = f2tf32(vv.y); vw.z = f2tf32(vv.z); vw.w = f2tf32(vv.w);
            *(float4*)&Ks[j * 68 + d4] = kw;
            *(float4*)&Vs[j * 72 + d4] = vw;
        }
        __syncthreads();

        float s[8][4];
#pragma unroll
        for (int nt = 0; nt < 8; nt++)
#pragma unroll
            for (int r = 0; r < 4; r++) s[nt][r] = 0.f;

#pragma unroll
        for (int ks = 0; ks < 8; ks++) {
            const int kb = ks * 8;
            uint32_t a[4];
            a[0] = __float_as_uint(Qs[(r0 + g    ) * 68 + kb + q    ]);
            a[1] = __float_as_uint(Qs[(r0 + g + 8) * 68 + kb + q    ]);
            a[2] = __float_as_uint(Qs[(r0 + g    ) * 68 + kb + q + 4]);
            a[3] = __float_as_uint(Qs[(r0 + g + 8) * 68 + kb + q + 4]);
#pragma unroll
            for (int nt = 0; nt < 8; nt++) {
                uint32_t bb[2];
                bb[0] = __float_as_uint(Ks[(nt * 8 + g) * 68 + kb + q    ]);
                bb[1] = __float_as_uint(Ks[(nt * 8 + g) * 68 + kb + q + 4]);
                mma_tf32(s[nt], a, bb);
            }
        }

        const int ig0 = qt * 64 + r0 + g;
        const int ig1 = ig0 + 8;
#pragma unroll
        for (int nt = 0; nt < 8; nt++) {
            const int jg = kt * 64 + nt * 8 + 2 * q;
            int d00 = ig0 - jg;     if (d00 < 0 || d00 >= WIN_) s[nt][0] = -1e30f;
            int d01 = ig0 - jg - 1; if (d01 < 0 || d01 >= WIN_) s[nt][1] = -1e30f;
            int d10 = ig1 - jg;     if (d10 < 0 || d10 >= WIN_) s[nt][2] = -1e30f;
            int d11 = ig1 - jg - 1; if (d11 < 0 || d11 >= WIN_) s[nt][3] = -1e30f;
        }
        float mx0 = -1e30f, mx1 = -1e30f;
#pragma unroll
        for (int nt = 0; nt < 8; nt++) {
            mx0 = fmaxf(mx0, fmaxf(s[nt][0], s[nt][1]));
            mx1 = fmaxf(mx1, fmaxf(s[nt][2], s[nt][3]));
        }
        mx0 = fmaxf(mx0, __shfl_xor_sync(0xffffffffu, mx0, 1));
        mx0 = fmaxf(mx0, __shfl_xor_sync(0xffffffffu, mx0, 2));
        mx1 = fmaxf(mx1, __shfl_xor_sync(0xffffffffu, mx1, 1));
        mx1 = fmaxf(mx1, __shfl_xor_sync(0xffffffffu, mx1, 2));

        const float mn0 = fmaxf(m0, mx0), mn1 = fmaxf(m1, mx1);
        const float e0 = __expf(m0 - mn0), e1 = __expf(m1 - mn1);
        float rs0 = 0.f, rs1 = 0.f;
#pragma unroll
        for (int nt = 0; nt < 8; nt++) {
            const float p00 = __expf(s[nt][0] - mn0);
            const float p01 = __expf(s[nt][1] - mn0);
            const float p10 = __expf(s[nt][2] - mn1);
            const float p11 = __expf(s[nt][3] - mn1);
            rs0 += p00 + p01;
            rs1 += p10 + p11;
            float2 v0 = make_float2(f2tf32(p00), f2tf32(p01));
            float2 v1 = make_float2(f2tf32(p10), f2tf32(p11));
            *(float2*)&Ps[(r0 + g    ) * 68 + nt * 8 + 2 * q] = v0;
            *(float2*)&Ps[(r0 + g + 8) * 68 + nt * 8 + 2 * q] = v1;
        }
        rs0 += __shfl_xor_sync(0xffffffffu, rs0, 1);
        rs0 += __shfl_xor_sync(0xffffffffu, rs0, 2);
        rs1 += __shfl_xor_sync(0xffffffffu, rs1, 1);
        rs1 += __shfl_xor_sync(0xffffffffu, rs1, 2);

        l0 = l0 * e0 + rs0;  m0 = mn0;
        l1 = l1 * e1 + rs1;  m1 = mn1;

#pragma unroll
        for (int nt = 0; nt < 8; nt++) {
            oc[nt][0] *= e0; oc[nt][1] *= e0;
            oc[nt][2] *= e1; oc[nt][3] *= e1;
        }
        __syncthreads();

#pragma unroll
        for (int ks = 0; ks < 8; ks++) {
            const int kb = ks * 8;
            uint32_t a[4];
            a[0] = __float_as_uint(Ps[(r0 + g    ) * 68 + kb + q    ]);
            a[1] = __float_as_uint(Ps[(r0 + g + 8) * 68 + kb + q    ]);
            a[2] = __float_as_uint(Ps[(r0 + g    ) * 68 + kb + q + 4]);
            a[3] = __float_as_uint(Ps[(r0 + g + 8) * 68 + kb + q + 4]);
#pragma unroll
            for (int nt = 0; nt < 8; nt++) {
                uint32_t bb[2];
                bb[0] = __float_as_uint(Vs[(kb + q    ) * 72 + nt * 8 + g]);
                bb[1] = __float_as_uint(Vs[(kb + q + 4) * 72 + nt * 8 + g]);
                mma_tf32(oc[nt], a, bb);
            }
        }
    }

    const float inv0 = 1.f / l0, inv1 = 1.f / l1;
    const int row0g = qt * 64 + r0 + g;
#pragma unroll
    for (int nt = 0; nt < 8; nt++) {
        const int col = h * HD_ + nt * 8 + 2 * q;
        float2 v0 = make_float2(f2tf32(oc[nt][0] * inv0), f2tf32(oc[nt][1] * inv0));
        float2 v1 = make_float2(f2tf32(oc[nt][2] * inv1), f2tf32(oc[nt][3] * inv1));
        *(float2*)&out[(size_t)(b * T_ + row0g    ) * H_ + col] = v0;
        *(float2*)&out[(size_t)(b * T_ + row0g + 8) * H_ + col] = v1;
    }
}

// ---------------------------------------------------------------------------
// Launch: repack(x, W) -> QKV GEMM -> attention -> repack(att) -> out GEMM
// ---------------------------------------------------------------------------
extern "C" void kernel_launch(void* const* d_in, const int* in_sizes, int n_in,
                              void* d_out, int out_size)
{
    const float* x     = (const float*)d_in[0];
    const float* W_qkv = (const float*)d_in[1];
    const float* b_qkv = (const float*)d_in[2];
    const float* W_out = (const float*)d_in[3];
    const float* b_out = (const float*)d_in[4];
    float* out = (float*)d_out;

    float* qkv;  cudaGetSymbolAddress((void**)&qkv,  g_qkv);
    float* att;  cudaGetSymbolAddress((void**)&att,  g_att);
    float* xp;   cudaGetSymbolAddress((void**)&xp,   g_xp);
    float* attp; cudaGetSymbolAddress((void**)&attp, g_attp);
    float* wqp;  cudaGetSymbolAddress((void**)&wqp,  g_wqkvp);
    float* wop;  cudaGetSymbolAddress((void**)&wop,  g_woutp);

    const int M = B_ * T_;   // 4096

    // 0) repack + tf32-round operands into fragment order
    {
        const int na = (M / 16) * (H_ / 8) * 32;            // x
        repack_a_kernel<<<(na + 255) / 256, 256>>>(x, xp, M, H_);
        const int nbq = ((3 * H_) / 8) * (H_ / 16) * 32;    // W_qkv
        repack_b_kernel<<<(nbq + 255) / 256, 256>>>(W_qkv, wqp, H_, 3 * H_);
        const int nbo = (H_ / 8) * (H_ / 16) * 32;          // W_out
        repack_b_kernel<<<(nbo + 255) / 256, 256>>>(W_out, wop, H_, H_);
    }

    cudaFuncSetAttribute(gemm_tf32_bias,
                         cudaFuncAttributeMaxDynamicSharedMemorySize, GEMM_SMEM);

    // 1) QKV projection: [4096,1024] @ [1024,3072] + bias
    {
        dim3 grid((3 * H_) / BN, M / BM);     // (24, 32)
        gemm_tf32_bias<<<grid, 128, GEMM_SMEM>>>(xp, wqp, b_qkv, qkv, M, 3 * H_, H_);
    }

    // 2) Banded attention
    {
        cudaFuncSetAttribute(attn_mma_kernel,
                             cudaFuncAttributeMaxDynamicSharedMemorySize, ATTN_SMEM2);
        dim3 grid(T_ / 64, NH_, B_);
        attn_mma_kernel<<<grid, 128, ATTN_SMEM2>>>(att);
    }

    // 2.5) repack attention output for GEMM2 A operand
    {
        const int na = (M / 16) * (H_ / 8) * 32;
        repack_a_kernel<<<(na + 255) / 256, 256>>>(att, attp, M, H_);
    }

    // 3) Output projection: [4096,1024] @ [1024,1024] + bias
    {
        dim3 grid(H_ / BN, M / BM);           // (8, 32)
        gemm_tf32_bias<<<grid, 128, GEMM_SMEM>>>(attp, wop, b_out, out, M, H_, H_);
    }
}

// round 15
// speedup vs baseline: 1.2343x; 1.0463x over previous
#include <cuda_runtime.h>
#include <math.h>
#include <stdint.h>

// Problem constants
#define B_    2
#define T_    2048
#define H_    1024
#define NH_   16
#define HD_   64
#define WIN_  256

// Scratch (device globals — allocation-free per harness rules)
__device__ float g_qkv[(size_t)B_ * T_ * 3 * H_];    // [B,T,3H]
__device__ float g_xp[(size_t)B_ * T_ * H_];         // x, fragment-permuted
__device__ float g_attp[(size_t)B_ * T_ * H_];       // attn out, fragment-permuted
__device__ float g_wqkvp[(size_t)H_ * 3 * H_];       // W_qkv, fragment-permuted
__device__ float g_woutp[(size_t)H_ * H_];           // W_out, fragment-permuted

__device__ __forceinline__ float f2tf32(float x) {
    uint32_t u;
    asm("cvt.rna.tf32.f32 %0, %1;" : "=r"(u) : "f"(x));
    return __uint_as_float(u);
}

__device__ __forceinline__ void mma_tf32(float c[4], const uint32_t a[4], const uint32_t b[2]) {
    asm volatile(
        "mma.sync.aligned.m16n8k8.row.col.f32.tf32.tf32.f32 "
        "{%0,%1,%2,%3}, {%4,%5,%6,%7}, {%8,%9}, {%0,%1,%2,%3};"
        : "+f"(c[0]), "+f"(c[1]), "+f"(c[2]), "+f"(c[3])
        : "r"(a[0]), "r"(a[1]), "r"(a[2]), "r"(a[3]), "r"(b[0]), "r"(b[1]));
}

__device__ __forceinline__ void cp_async16(void* smem_dst, const void* gsrc) {
    uint32_t s = (uint32_t)__cvta_generic_to_shared(smem_dst);
    asm volatile("cp.async.cg.shared.global [%0], [%1], 16;" :: "r"(s), "l"(gsrc));
}
__device__ __forceinline__ void cp_commit() {
    asm volatile("cp.async.commit_group;");
}
template <int N>
__device__ __forceinline__ void cp_wait() {
    asm volatile("cp.async.wait_group %0;" :: "n"(N));
}

// Quad butterfly: convert C-fragment layout {row g col 2q, row g col 2q+1,
// row g+8 col 2q, row g+8 col 2q+1} to A-fragment layout {row g col q,
// row g+8 col q, row g col q+4, row g+8 col q+4} within each 4-lane quad.
__device__ __forceinline__ void quad_to_afrag(const float p[4], float f[4]) {
    const int lane = threadIdx.x & 31;
    const int q = lane & 3;
    const int srcA = (lane & ~3) | (q >> 1);
    const int srcB = srcA + 2;
    float a0 = __shfl_sync(0xffffffffu, p[0], srcA);
    float a1 = __shfl_sync(0xffffffffu, p[1], srcA);
    float a2 = __shfl_sync(0xffffffffu, p[2], srcA);
    float a3 = __shfl_sync(0xffffffffu, p[3], srcA);
    float b0 = __shfl_sync(0xffffffffu, p[0], srcB);
    float b1 = __shfl_sync(0xffffffffu, p[1], srcB);
    float b2 = __shfl_sync(0xffffffffu, p[2], srcB);
    float b3 = __shfl_sync(0xffffffffu, p[3], srcB);
    const bool odd = (q & 1) != 0;
    f[0] = odd ? a1 : a0;   // row g,   col q
    f[1] = odd ? a3 : a2;   // row g+8, col q
    f[2] = odd ? b1 : b0;   // row g,   col q+4
    f[3] = odd ? b3 : b2;   // row g+8, col q+4
}

// ---------------------------------------------------------------------------
// Repack A: src [M][K] row-major fp32 -> dst fragment-permuted + tf32-rounded.
// ---------------------------------------------------------------------------
__global__ void repack_a_kernel(const float* __restrict__ src,
                                float* __restrict__ dst, int M, int K)
{
    const int idx = blockIdx.x * blockDim.x + threadIdx.x;
    const int total = (M >> 4) * (K >> 3) * 32;
    if (idx >= total) return;
    const int lane = idx & 31;
    const int kt   = (idx >> 5) % (K >> 3);
    const int mt   = idx / (32 * (K >> 3));
    const int grp = lane >> 2, qid = lane & 3;
    const int r0 = mt * 16 + grp, c0 = kt * 8 + qid;
    float4 v;
    v.x = f2tf32(src[(size_t)r0 * K + c0]);
    v.y = f2tf32(src[(size_t)(r0 + 8) * K + c0]);
    v.z = f2tf32(src[(size_t)r0 * K + c0 + 4]);
    v.w = f2tf32(src[(size_t)(r0 + 8) * K + c0 + 4]);
    ((float4*)dst)[idx] = v;
}

// ---------------------------------------------------------------------------
// Repack B: src [K][N] row-major fp32 -> fragment-permuted + tf32-rounded.
// ---------------------------------------------------------------------------
__global__ void repack_b_kernel(const float* __restrict__ src,
                                float* __restrict__ dst, int K, int N)
{
    const int idx = blockIdx.x * blockDim.x + threadIdx.x;
    const int total = (N >> 3) * (K >> 4) * 32;
    if (idx >= total) return;
    const int lane = idx & 31;
    const int kp   = (idx >> 5) % (K >> 4);
    const int nt   = idx / (32 * (K >> 4));
    const int grp = lane >> 2, qid = lane & 3;
    const int c = nt * 8 + grp, r = kp * 16;
    float4 v;
    v.x = f2tf32(src[(size_t)(r + qid     ) * N + c]);
    v.y = f2tf32(src[(size_t)(r + qid +  4) * N + c]);
    v.z = f2tf32(src[(size_t)(r + qid +  8) * N + c]);
    v.w = f2tf32(src[(size_t)(r + qid + 12) * N + c]);
    ((float4*)dst)[idx] = v;
}

// ---------------------------------------------------------------------------
// TF32 tensor-core GEMM on fragment-permuted operands. (R14 winner, unchanged)
// CTA 128x128, 128 threads = 4 warps (2x2), warp tile 64x64, BK=32,
// 3-stage cp.async pipeline, 2 CTAs/SM.
// ---------------------------------------------------------------------------
#define BM 128
#define BN 128
#define BK 32
#define NSTAGE 3
#define A_STAGE_BYTES (8 * 4 * 32 * 16)
#define B_STAGE_BYTES (16 * 2 * 32 * 16)
#define STAGE_BYTES   (A_STAGE_BYTES + B_STAGE_BYTES)
#define GEMM_SMEM     (NSTAGE * STAGE_BYTES)

__global__ __launch_bounds__(128, 2)
void gemm_tf32_bias(const float* __restrict__ Ap, const float* __restrict__ Bp,
                    const float* __restrict__ bias, float* __restrict__ C,
                    int M, int N, int K)
{
    extern __shared__ char smem[];

    const int tid  = threadIdx.x;
    const int wid  = tid >> 5;
    const int lane = tid & 31;
    const int wm   = wid >> 1;
    const int wn   = wid & 1;
    const int grp  = lane >> 2;
    const int qid  = lane & 3;
    const int bx = blockIdx.x, by = blockIdx.y;

    const int KT = K >> 3;
    const int KP = K >> 4;

    float acc[4][8][4];
#pragma unroll
    for (int m = 0; m < 4; m++)
#pragma unroll
        for (int n = 0; n < 8; n++)
#pragma unroll
            for (int r = 0; r < 4; r++) acc[m][n][r] = 0.f;

    const int NCH = K / BK;

    auto load_stage = [&](int it, int s) {
        char* As = smem + s * STAGE_BYTES;
        char* Bs = As + A_STAGE_BYTES;
#pragma unroll
        for (int i = 0; i < 8; i++) {
            const int f = tid + i * 128;
            const int mloc = f >> 7;
            const int rest = f & 127;
            const size_t srcidx = ((size_t)(by * 8 + mloc) * KT + it * 4) * 32 + rest;
            cp_async16(As + f * 16, Ap + srcidx * 4);
        }
#pragma unroll
        for (int i = 0; i < 8; i++) {
            const int f = tid + i * 128;
            const int ntloc = f >> 6;
            const int rest = f & 63;
            const size_t srcidx = ((size_t)(bx * 16 + ntloc) * KP + it * 2) * 32 + rest;
            cp_async16(Bs + f * 16, Bp + srcidx * 4);
        }
        cp_commit();
    };

    load_stage(0, 0);
    load_stage(1, 1);

    int stage = 0;
    for (int it = 0; it < NCH; it++) {
        if (it + 1 < NCH) cp_wait<1>(); else cp_wait<0>();
        __syncthreads();

        if (it + 2 < NCH) {
            int s2 = stage + 2; if (s2 >= NSTAGE) s2 -= NSTAGE;
            load_stage(it + 2, s2);
        }

        const char* As = smem + stage * STAGE_BYTES;
        const char* Bs = As + A_STAGE_BYTES;

#pragma unroll
        for (int kp = 0; kp < 2; kp++) {
            uint4 bfrag[8];
#pragma unroll
            for (int n = 0; n < 8; n++)
                bfrag[n] = *(const uint4*)(Bs + ((((wn * 8 + n) * 2 + kp) * 32 + lane) << 4));
#pragma unroll
            for (int half = 0; half < 2; half++) {
                uint4 afrag[4];
#pragma unroll
                for (int m = 0; m < 4; m++)
                    afrag[m] = *(const uint4*)(As + ((((wm * 4 + m) * 4 + kp * 2 + half) * 32 + lane) << 4));
#pragma unroll
                for (int m = 0; m < 4; m++) {
                    const uint32_t a[4] = {afrag[m].x, afrag[m].y, afrag[m].z, afrag[m].w};
#pragma unroll
                    for (int n = 0; n < 8; n++) {
                        const uint32_t b[2] = {half ? bfrag[n].z : bfrag[n].x,
                                               half ? bfrag[n].w : bfrag[n].y};
                        mma_tf32(acc[m][n], a, b);
                    }
                }
            }
        }

        stage = stage + 1; if (stage >= NSTAGE) stage -= NSTAGE;
    }

#pragma unroll
    for (int m = 0; m < 4; m++) {
        const int row0 = by * BM + wm * 64 + m * 16 + grp;
#pragma unroll
        for (int n = 0; n < 8; n++) {
            const int col = bx * BN + wn * 64 + n * 8 + qid * 2;
            const float b0 = bias[col], b1 = bias[col + 1];
            float2 v0 = make_float2(acc[m][n][0] + b0, acc[m][n][1] + b1);
            float2 v1 = make_float2(acc[m][n][2] + b0, acc[m][n][3] + b1);
            *(float2*)(C + (size_t)row0 * N + col)       = v0;
            *(float2*)(C + (size_t)(row0 + 8) * N + col) = v1;
        }
    }
}

// ---------------------------------------------------------------------------
// Banded causal attention on tensor cores, v2:
//  - Q fragments hoisted into registers (loaded once per block)
//  - P stays in registers via quad butterfly (no Ps smem, one less barrier/kt)
//  - epilogue writes fragment-permuted output directly to g_attp (STG.128)
// smem: Qs[64][68] + Ks[64][68] + Vs[64][72] = 53,248 B.
// ---------------------------------------------------------------------------
#define ATTN_SMEM3 ((64*68*2 + 64*72) * 4)

__global__ __launch_bounds__(128)
void attn_mma_kernel(float* __restrict__ outp)
{
    extern __shared__ float sm[];
    float* Qs = sm;                   // [64][68]
    float* Ks = sm + 64 * 68;         // [64][68]
    float* Vs = sm + 2 * 64 * 68;     // [64][72]

    const int qt  = blockIdx.x;
    const int h   = blockIdx.y;
    const int b   = blockIdx.z;
    const int tid = threadIdx.x;
    const int wid  = tid >> 5;
    const int lane = tid & 31;
    const int g = lane >> 2;
    const int q = lane & 3;
    const int r0 = wid * 16;

    const size_t rs = 3 * H_;
    const size_t base_bt = (size_t)b * T_ * rs + (size_t)h * HD_;
    const size_t qbase = base_bt + (size_t)(qt * 64) * rs;

    // Load Q tile (scaled by 1/8, tf32-rounded) into smem
#pragma unroll
    for (int it = 0; it < 8; it++) {
        const int idx = tid + it * 128;
        const int i = idx >> 4, d4 = (idx & 15) << 2;
        float4 v = *(const float4*)&g_qkv[qbase + (size_t)i * rs + d4];
        float4 w;
        w.x = f2tf32(v.x * 0.125f);
        w.y = f2tf32(v.y * 0.125f);
        w.z = f2tf32(v.z * 0.125f);
        w.w = f2tf32(v.w * 0.125f);
        *(float4*)&Qs[i * 68 + d4] = w;
    }
    __syncthreads();

    // Hoist Q fragments into registers (reused across all kt)
    uint32_t qf[8][4];
#pragma unroll
    for (int ks = 0; ks < 8; ks++) {
        const int kb = ks * 8;
        qf[ks][0] = __float_as_uint(Qs[(r0 + g    ) * 68 + kb + q    ]);
        qf[ks][1] = __float_as_uint(Qs[(r0 + g + 8) * 68 + kb + q    ]);
        qf[ks][2] = __float_as_uint(Qs[(r0 + g    ) * 68 + kb + q + 4]);
        qf[ks][3] = __float_as_uint(Qs[(r0 + g + 8) * 68 + kb + q + 4]);
    }

    float oc[8][4];
#pragma unroll
    for (int nt = 0; nt < 8; nt++)
#pragma unroll
        for (int r = 0; r < 4; r++) oc[nt][r] = 0.f;

    float m0 = -1e30f, m1 = -1e30f, l0 = 0.f, l1 = 0.f;

    int kt0 = qt - 4; if (kt0 < 0) kt0 = 0;

    for (int kt = kt0; kt <= qt; kt++) {
        __syncthreads();   // all warps done reading Ks/Vs of previous kt

        const size_t kbase = base_bt + (size_t)(kt * 64) * rs + H_;
#pragma unroll
        for (int it = 0; it < 8; it++) {
            const int idx = tid + it * 128;
            const int j = idx >> 4, d4 = (idx & 15) << 2;
            float4 kv = *(const float4*)&g_qkv[kbase + (size_t)j * rs + d4];
            float4 vv = *(const float4*)&g_qkv[kbase + H_ + (size_t)j * rs + d4];
            float4 kw, vw;
            kw.x = f2tf32(kv.x); kw.y = f2tf32(kv.y); kw.z = f2tf32(kv.z); kw.w = f2tf32(kv.w);
            vw.x = f2tf32(vv.x); vw.y = f2tf32(vv.y); vw.z = f2tf32(vv.z); vw.w = f2tf32(vv.w);
            *(float4*)&Ks[j * 68 + d4] = kw;
            *(float4*)&Vs[j * 72 + d4] = vw;
        }
        __syncthreads();

        // ---- S = Q @ K^T ----
        float s[8][4];
#pragma unroll
        for (int nt = 0; nt < 8; nt++)
#pragma unroll
            for (int r = 0; r < 4; r++) s[nt][r] = 0.f;

#pragma unroll
        for (int ks = 0; ks < 8; ks++) {
            const int kb = ks * 8;
#pragma unroll
            for (int nt = 0; nt < 8; nt++) {
                uint32_t bb[2];
                bb[0] = __float_as_uint(Ks[(nt * 8 + g) * 68 + kb + q    ]);
                bb[1] = __float_as_uint(Ks[(nt * 8 + g) * 68 + kb + q + 4]);
                mma_tf32(s[nt], qf[ks], bb);
            }
        }

        // ---- mask + warp-local online softmax ----
        const int ig0 = qt * 64 + r0 + g;
        const int ig1 = ig0 + 8;
#pragma unroll
        for (int nt = 0; nt < 8; nt++) {
            const int jg = kt * 64 + nt * 8 + 2 * q;
            int d00 = ig0 - jg;     if (d00 < 0 || d00 >= WIN_) s[nt][0] = -1e30f;
            int d01 = ig0 - jg - 1; if (d01 < 0 || d01 >= WIN_) s[nt][1] = -1e30f;
            int d10 = ig1 - jg;     if (d10 < 0 || d10 >= WIN_) s[nt][2] = -1e30f;
            int d11 = ig1 - jg - 1; if (d11 < 0 || d11 >= WIN_) s[nt][3] = -1e30f;
        }
        float mx0 = -1e30f, mx1 = -1e30f;
#pragma unroll
        for (int nt = 0; nt < 8; nt++) {
            mx0 = fmaxf(mx0, fmaxf(s[nt][0], s[nt][1]));
            mx1 = fmaxf(mx1, fmaxf(s[nt][2], s[nt][3]));
        }
        mx0 = fmaxf(mx0, __shfl_xor_sync(0xffffffffu, mx0, 1));
        mx0 = fmaxf(mx0, __shfl_xor_sync(0xffffffffu, mx0, 2));
        mx1 = fmaxf(mx1, __shfl_xor_sync(0xffffffffu, mx1, 1));
        mx1 = fmaxf(mx1, __shfl_xor_sync(0xffffffffu, mx1, 2));

        const float mn0 = fmaxf(m0, mx0), mn1 = fmaxf(m1, mx1);
        const float e0 = __expf(m0 - mn0), e1 = __expf(m1 - mn1);
        float rs0 = 0.f, rs1 = 0.f;

        // P in registers: compute exp, round, butterfly to A-fragment layout
        uint32_t pf[8][4];
#pragma unroll
        for (int nt = 0; nt < 8; nt++) {
            float p[4], f[4];
            p[0] = __expf(s[nt][0] - mn0);
            p[1] = __expf(s[nt][1] - mn0);
            p[2] = __expf(s[nt][2] - mn1);
            p[3] = __expf(s[nt][3] - mn1);
            rs0 += p[0] + p[1];
            rs1 += p[2] + p[3];
            p[0] = f2tf32(p[0]); p[1] = f2tf32(p[1]);
            p[2] = f2tf32(p[2]); p[3] = f2tf32(p[3]);
            quad_to_afrag(p, f);
            pf[nt][0] = __float_as_uint(f[0]);
            pf[nt][1] = __float_as_uint(f[1]);
            pf[nt][2] = __float_as_uint(f[2]);
            pf[nt][3] = __float_as_uint(f[3]);
        }
        rs0 += __shfl_xor_sync(0xffffffffu, rs0, 1);
        rs0 += __shfl_xor_sync(0xffffffffu, rs0, 2);
        rs1 += __shfl_xor_sync(0xffffffffu, rs1, 1);
        rs1 += __shfl_xor_sync(0xffffffffu, rs1, 2);

        l0 = l0 * e0 + rs0;  m0 = mn0;
        l1 = l1 * e1 + rs1;  m1 = mn1;

#pragma unroll
        for (int nt = 0; nt < 8; nt++) {
            oc[nt][0] *= e0; oc[nt][1] *= e0;
            oc[nt][2] *= e1; oc[nt][3] *= e1;
        }

        // ---- O += P @ V (P fragments in registers, no barrier needed) ----
#pragma unroll
        for (int ks = 0; ks < 8; ks++) {
            const int kb = ks * 8;
#pragma unroll
            for (int nt = 0; nt < 8; nt++) {
                uint32_t bb[2];
                bb[0] = __float_as_uint(Vs[(kb + q    ) * 72 + nt * 8 + g]);
                bb[1] = __float_as_uint(Vs[(kb + q + 4) * 72 + nt * 8 + g]);
                mma_tf32(oc[nt], pf[ks], bb);
            }
        }
    }

    // ---- normalize + butterfly + write fragment-permuted output ----
    const float inv0 = 1.f / l0, inv1 = 1.f / l1;
    const int mt = (b * T_ + qt * 64 + r0) >> 4;   // 16-row tile index
#pragma unroll
    for (int nt = 0; nt < 8; nt++) {
        float p[4], f[4];
        p[0] = f2tf32(oc[nt][0] * inv0);
        p[1] = f2tf32(oc[nt][1] * inv0);
        p[2] = f2tf32(oc[nt][2] * inv1);
        p[3] = f2tf32(oc[nt][3] * inv1);
        quad_to_afrag(p, f);
        const size_t chunk = ((size_t)mt * (H_ / 8) + (h * 8 + nt)) * 32 + lane;
        float4 v = make_float4(f[0], f[1], f[2], f[3]);
        ((float4*)outp)[chunk] = v;
    }
}

// ---------------------------------------------------------------------------
// Launch: repack(x, W) -> QKV GEMM -> attention (writes attp) -> out GEMM
// ---------------------------------------------------------------------------
extern "C" void kernel_launch(void* const* d_in, const int* in_sizes, int n_in,
                              void* d_out, int out_size)
{
    const float* x     = (const float*)d_in[0];
    const float* W_qkv = (const float*)d_in[1];
    const float* b_qkv = (const float*)d_in[2];
    const float* W_out = (const float*)d_in[3];
    const float* b_out = (const float*)d_in[4];
    float* out = (float*)d_out;

    float* qkv;  cudaGetSymbolAddress((void**)&qkv,  g_qkv);
    float* xp;   cudaGetSymbolAddress((void**)&xp,   g_xp);
    float* attp; cudaGetSymbolAddress((void**)&attp, g_attp);
    float* wqp;  cudaGetSymbolAddress((void**)&wqp,  g_wqkvp);
    float* wop;  cudaGetSymbolAddress((void**)&wop,  g_woutp);

    const int M = B_ * T_;   // 4096

    // 0) repack + tf32-round operands into fragment order
    {
        const int na = (M / 16) * (H_ / 8) * 32;
        repack_a_kernel<<<(na + 255) / 256, 256>>>(x, xp, M, H_);
        const int nbq = ((3 * H_) / 8) * (H_ / 16) * 32;
        repack_b_kernel<<<(nbq + 255) / 256, 256>>>(W_qkv, wqp, H_, 3 * H_);
        const int nbo = (H_ / 8) * (H_ / 16) * 32;
        repack_b_kernel<<<(nbo + 255) / 256, 256>>>(W_out, wop, H_, H_);
    }

    cudaFuncSetAttribute(gemm_tf32_bias,
                         cudaFuncAttributeMaxDynamicSharedMemorySize, GEMM_SMEM);

    // 1) QKV projection: [4096,1024] @ [1024,3072] + bias
    {
        dim3 grid((3 * H_) / BN, M / BM);     // (24, 32)
        gemm_tf32_bias<<<grid, 128, GEMM_SMEM>>>(xp, wqp, b_qkv, qkv, M, 3 * H_, H_);
    }

    // 2) Banded attention -> fragment-permuted output directly
    {
        cudaFuncSetAttribute(attn_mma_kernel,
                             cudaFuncAttributeMaxDynamicSharedMemorySize, ATTN_SMEM3);
        dim3 grid(T_ / 64, NH_, B_);
        attn_mma_kernel<<<grid, 128, ATTN_SMEM3>>>(attp);
    }

    // 3) Output projection: [4096,1024] @ [1024,1024] + bias
    {
        dim3 grid(H_ / BN, M / BM);           // (8, 32)
        gemm_tf32_bias<<<grid, 128, GEMM_SMEM>>>(attp, wop, b_out, out, M, H_, H_);
    }
}

// round 17
// speedup vs baseline: 2.1883x; 1.7730x over previous
#include <cuda_runtime.h>
#include <cuda_fp16.h>
#include <math.h>
#include <stdint.h>

// Problem constants
#define B_    2
#define T_    2048
#define H_    1024
#define NH_   16
#define HD_   64
#define WIN_  256

// Scratch (device globals — allocation-free per harness rules)
__device__ __half g_qkv[(size_t)B_ * T_ * 3 * H_];   // [B,T,3H] fp16
__device__ __half g_xp[(size_t)B_ * T_ * H_];        // x, A-fragment-permuted fp16
__device__ __half g_attp[(size_t)B_ * T_ * H_];      // attn out, A-frag-permuted fp16
__device__ __half g_wqkvp[(size_t)H_ * 3 * H_];      // W_qkv, B-frag-permuted fp16
__device__ __half g_woutp[(size_t)H_ * H_];          // W_out, B-frag-permuted fp16

__device__ __forceinline__ uint32_t pack_h2(float lo, float hi) {
    uint32_t r;
    asm("cvt.rn.f16x2.f32 %0, %1, %2;" : "=r"(r) : "f"(hi), "f"(lo));
    return r;
}
__device__ __forceinline__ uint32_t mul_h2(uint32_t u, uint32_t s) {
    uint32_t r;
    asm("mul.rn.f16x2 %0, %1, %2;" : "=r"(r) : "r"(u), "r"(s));
    return r;
}

// m16n8k16 fp16 MMA, fp32 accumulate
__device__ __forceinline__ void mma_fp16(float c[4], const uint32_t a[4], const uint32_t b[2]) {
    asm volatile(
        "mma.sync.aligned.m16n8k16.row.col.f32.f16.f16.f32 "
        "{%0,%1,%2,%3}, {%4,%5,%6,%7}, {%8,%9}, {%0,%1,%2,%3};"
        : "+f"(c[0]), "+f"(c[1]), "+f"(c[2]), "+f"(c[3])
        : "r"(a[0]), "r"(a[1]), "r"(a[2]), "r"(a[3]), "r"(b[0]), "r"(b[1]));
}

__device__ __forceinline__ void cp_async16(void* smem_dst, const void* gsrc) {
    uint32_t s = (uint32_t)__cvta_generic_to_shared(smem_dst);
    asm volatile("cp.async.cg.shared.global [%0], [%1], 16;" :: "r"(s), "l"(gsrc));
}
__device__ __forceinline__ void cp_commit() {
    asm volatile("cp.async.commit_group;");
}
template <int N>
__device__ __forceinline__ void cp_wait() {
    asm volatile("cp.async.wait_group %0;" :: "n"(N));
}

// ---------------------------------------------------------------------------
// Repack A: src [M][K] fp32 row-major -> fp16 A-fragment chunks.
// chunk idx = (mt*(K/16) + kt)*32 + lane; 16B = 8 halves = one thread's
// m16n8k16 A fragment.
// ---------------------------------------------------------------------------
__global__ void repack_a_fp16(const float* __restrict__ src,
                              __half* __restrict__ dst, int M, int K)
{
    const int idx = blockIdx.x * blockDim.x + threadIdx.x;
    const int total = (M >> 4) * (K >> 4) * 32;
    if (idx >= total) return;
    const int lane = idx & 31;
    const int kt   = (idx >> 5) % (K >> 4);
    const int mt   = idx / (32 * (K >> 4));
    const int g = lane >> 2, q = lane & 3;
    const int r0 = mt * 16 + g, c0 = kt * 16 + 2 * q;
    uint4 v;
    v.x = pack_h2(src[(size_t)r0 * K + c0],           src[(size_t)r0 * K + c0 + 1]);
    v.y = pack_h2(src[(size_t)(r0 + 8) * K + c0],     src[(size_t)(r0 + 8) * K + c0 + 1]);
    v.z = pack_h2(src[(size_t)r0 * K + c0 + 8],       src[(size_t)r0 * K + c0 + 9]);
    v.w = pack_h2(src[(size_t)(r0 + 8) * K + c0 + 8], src[(size_t)(r0 + 8) * K + c0 + 9]);
    ((uint4*)dst)[idx] = v;
}

// ---------------------------------------------------------------------------
// Repack B: src [K][N] fp32 row-major -> fp16 B-fragment chunks.
// chunk idx = (nt*(K/32) + kp)*32 + lane; 16B = 2 k16 B-fragments.
// ---------------------------------------------------------------------------
__global__ void repack_b_fp16(const float* __restrict__ src,
                              __half* __restrict__ dst, int K, int N)
{
    const int idx = blockIdx.x * blockDim.x + threadIdx.x;
    const int total = (N >> 3) * (K >> 5) * 32;
    if (idx >= total) return;
    const int lane = idx & 31;
    const int kp   = (idx >> 5) % (K >> 5);
    const int nt   = idx / (32 * (K >> 5));
    const int g = lane >> 2, q = lane & 3;
    const int c = nt * 8 + g, r = kp * 32 + 2 * q;
    uint4 v;
    v.x = pack_h2(src[(size_t)r * N + c],        src[(size_t)(r + 1) * N + c]);
    v.y = pack_h2(src[(size_t)(r + 8) * N + c],  src[(size_t)(r + 9) * N + c]);
    v.z = pack_h2(src[(size_t)(r + 16) * N + c], src[(size_t)(r + 17) * N + c]);
    v.w = pack_h2(src[(size_t)(r + 24) * N + c], src[(size_t)(r + 25) * N + c]);
    ((uint4*)dst)[idx] = v;
}

// ---------------------------------------------------------------------------
// FP16 tensor-core GEMM on fragment-permuted operands.
// CTA 128x128, 4 warps (2x2), warp tile 64x64, BK=32, 3-stage cp.async,
// 2 CTAs/SM. Per chunk per warp: 16 LDS.128, 64 MMAs (m16n8k16).
// ---------------------------------------------------------------------------
#define BM 128
#define BN 128
#define BK 32
#define NSTAGE 3
#define A_STAGE_BYTES (8 * 2 * 32 * 16)
#define B_STAGE_BYTES (16 * 1 * 32 * 16)
#define STAGE_BYTES   (A_STAGE_BYTES + B_STAGE_BYTES)
#define GEMM_SMEM     (NSTAGE * STAGE_BYTES)

template <bool HALF_OUT>
__global__ __launch_bounds__(128, 2)
void gemm_fp16_bias(const __half* __restrict__ Ap, const __half* __restrict__ Bp,
                    const float* __restrict__ bias, void* __restrict__ Cv,
                    int M, int N, int K)
{
    extern __shared__ char smem[];

    const int tid  = threadIdx.x;
    const int wid  = tid >> 5;
    const int lane = tid & 31;
    const int wm   = wid >> 1;
    const int wn   = wid & 1;
    const int g    = lane >> 2;
    const int q    = lane & 3;
    const int bx = blockIdx.x, by = blockIdx.y;

    const int KT16 = K >> 4;
    const int KT32 = K >> 5;

    float acc[4][8][4];
#pragma unroll
    for (int m = 0; m < 4; m++)
#pragma unroll
        for (int n = 0; n < 8; n++)
#pragma unroll
            for (int r = 0; r < 4; r++) acc[m][n][r] = 0.f;

    const int NCH = K / BK;

    auto load_stage = [&](int it, int s) {
        char* As = smem + s * STAGE_BYTES;
        char* Bs = As + A_STAGE_BYTES;
#pragma unroll
        for (int i = 0; i < 4; i++) {
            const int f = tid + i * 128;
            const int mloc = f >> 6;
            const int rest = f & 63;
            const size_t srcidx = ((size_t)(by * 8 + mloc) * KT16 + it * 2) * 32 + rest;
            cp_async16(As + f * 16, (const char*)Ap + srcidx * 16);
        }
#pragma unroll
        for (int i = 0; i < 4; i++) {
            const int f = tid + i * 128;
            const int ntloc = f >> 5;
            const int l2 = f & 31;
            const size_t srcidx = ((size_t)(bx * 16 + ntloc) * KT32 + it) * 32 + l2;
            cp_async16(Bs + f * 16, (const char*)Bp + srcidx * 16);
        }
        cp_commit();
    };

    load_stage(0, 0);
    load_stage(1, 1);

    int stage = 0;
    for (int it = 0; it < NCH; it++) {
        if (it + 1 < NCH) cp_wait<1>(); else cp_wait<0>();
        __syncthreads();

        if (it + 2 < NCH) {
            int s2 = stage + 2; if (s2 >= NSTAGE) s2 -= NSTAGE;
            load_stage(it + 2, s2);
        }

        const char* As = smem + stage * STAGE_BYTES;
        const char* Bs = As + A_STAGE_BYTES;

        uint4 bf[8];
#pragma unroll
        for (int n = 0; n < 8; n++)
            bf[n] = *(const uint4*)(Bs + (((wn * 8 + n) * 32 + lane) << 4));

#pragma unroll
        for (int ks = 0; ks < 2; ks++) {
            uint4 af[4];
#pragma unroll
            for (int m = 0; m < 4; m++)
                af[m] = *(const uint4*)(As + ((((wm * 4 + m) * 2 + ks) * 32 + lane) << 4));
#pragma unroll
            for (int m = 0; m < 4; m++) {
                const uint32_t a[4] = {af[m].x, af[m].y, af[m].z, af[m].w};
#pragma unroll
                for (int n = 0; n < 8; n++) {
                    const uint32_t b[2] = {ks ? bf[n].z : bf[n].x,
                                           ks ? bf[n].w : bf[n].y};
                    mma_fp16(acc[m][n], a, b);
                }
            }
        }

        stage = stage + 1; if (stage >= NSTAGE) stage -= NSTAGE;
    }

    // Epilogue with bias
#pragma unroll
    for (int m = 0; m < 4; m++) {
        const int row0 = by * BM + wm * 64 + m * 16 + g;
#pragma unroll
        for (int n = 0; n < 8; n++) {
            const int col = bx * BN + wn * 64 + n * 8 + q * 2;
            const float b0 = bias[col], b1 = bias[col + 1];
            const float v00 = acc[m][n][0] + b0, v01 = acc[m][n][1] + b1;
            const float v10 = acc[m][n][2] + b0, v11 = acc[m][n][3] + b1;
            if (HALF_OUT) {
                __half* C = (__half*)Cv;
                *(uint32_t*)(C + (size_t)row0 * N + col)       = pack_h2(v00, v01);
                *(uint32_t*)(C + (size_t)(row0 + 8) * N + col) = pack_h2(v10, v11);
            } else {
                float* C = (float*)Cv;
                *(float2*)(C + (size_t)row0 * N + col)       = make_float2(v00, v01);
                *(float2*)(C + (size_t)(row0 + 8) * N + col) = make_float2(v10, v11);
            }
        }
    }
}

// ---------------------------------------------------------------------------
// Banded causal attention, fp16 m16n8k16, flash online softmax.
// Block 128 threads (4 warps); warp = 16 query rows x 64 cols.
// smem (uint32 words): Qs[64][36] | Ks[64][36] | Vs2[32][68] half2
// ---------------------------------------------------------------------------
#define QS_W 0
#define KS_W 2304
#define VS_W 4608
#define ATTN_SMEM4 ((4608 + 32 * 68) * 4)   // 27136 B

__global__ __launch_bounds__(128)
void attn_fp16_kernel(__half* __restrict__ outp)
{
    extern __shared__ uint32_t smw[];

    const int qt  = blockIdx.x;
    const int h   = blockIdx.y;
    const int b   = blockIdx.z;
    const int tid = threadIdx.x;
    const int wid  = tid >> 5;
    const int lane = tid & 31;
    const int g = lane >> 2;
    const int q = lane & 3;
    const int r0 = wid * 16;

    const size_t rs = 3 * H_;
    const size_t base_bt = (size_t)b * T_ * rs + (size_t)h * HD_;
    const size_t qbase = base_bt + (size_t)(qt * 64) * rs;

    // ---- load Q tile (x 0.125, exact in fp16) ----
    const uint32_t scale8 = 0x30003000u;   // half2(0.125, 0.125)
#pragma unroll
    for (int it = 0; it < 4; it++) {
        const int f = tid + it * 128;          // 0..511
        const int i = f >> 3, d8 = (f & 7) * 8;
        uint4 v = *(const uint4*)&g_qkv[qbase + (size_t)i * rs + d8];
        v.x = mul_h2(v.x, scale8); v.y = mul_h2(v.y, scale8);
        v.z = mul_h2(v.z, scale8); v.w = mul_h2(v.w, scale8);
        *(uint4*)&smw[QS_W + i * 36 + d8 / 2] = v;
    }
    __syncthreads();

    // ---- hoist Q fragments (4 k16-tiles) for THIS WARP'S rows (r0!) ----
    uint32_t qf[4][4];
#pragma unroll
    for (int kt = 0; kt < 4; kt++) {
        qf[kt][0] = smw[QS_W + (r0 + g    ) * 36 + kt * 8 + q];
        qf[kt][1] = smw[QS_W + (r0 + g + 8) * 36 + kt * 8 + q];
        qf[kt][2] = smw[QS_W + (r0 + g    ) * 36 + kt * 8 + q + 4];
        qf[kt][3] = smw[QS_W + (r0 + g + 8) * 36 + kt * 8 + q + 4];
    }

    float oc[8][4];
#pragma unroll
    for (int nt = 0; nt < 8; nt++)
#pragma unroll
        for (int r = 0; r < 4; r++) oc[nt][r] = 0.f;

    float m0 = -1e30f, m1 = -1e30f, l0 = 0.f, l1 = 0.f;

    int kt0 = qt - 4; if (kt0 < 0) kt0 = 0;

    for (int kt = kt0; kt <= qt; kt++) {
        __syncthreads();   // previous iter done reading Ks/Vs

        const size_t kbase = base_bt + (size_t)(kt * 64) * rs + H_;
#pragma unroll
        for (int it = 0; it < 4; it++) {
            const int f = tid + it * 128;
            const int j = f >> 3, d8 = (f & 7) * 8;
            uint4 v = *(const uint4*)&g_qkv[kbase + (size_t)j * rs + d8];
            *(uint4*)&smw[KS_W + j * 36 + d8 / 2] = v;
        }
        const size_t vbase = kbase + H_;
#pragma unroll
        for (int it = 0; it < 2; it++) {
            const int f = tid + it * 128;
            const int jj = f >> 3, d8 = (f & 7) * 8;
            uint4 a = *(const uint4*)&g_qkv[vbase + (size_t)(2 * jj) * rs + d8];
            uint4 bb = *(const uint4*)&g_qkv[vbase + (size_t)(2 * jj + 1) * rs + d8];
            uint4 z0, z1;
            z0.x = __byte_perm(a.x, bb.x, 0x5410); z0.y = __byte_perm(a.x, bb.x, 0x7632);
            z0.z = __byte_perm(a.y, bb.y, 0x5410); z0.w = __byte_perm(a.y, bb.y, 0x7632);
            z1.x = __byte_perm(a.z, bb.z, 0x5410); z1.y = __byte_perm(a.z, bb.z, 0x7632);
            z1.z = __byte_perm(a.w, bb.w, 0x5410); z1.w = __byte_perm(a.w, bb.w, 0x7632);
            *(uint4*)&smw[VS_W + jj * 68 + d8]     = z0;
            *(uint4*)&smw[VS_W + jj * 68 + d8 + 4] = z1;
        }
        __syncthreads();

        // ---- S = Q @ K^T ----
        float s[8][4];
#pragma unroll
        for (int nt = 0; nt < 8; nt++)
#pragma unroll
            for (int r = 0; r < 4; r++) s[nt][r] = 0.f;

#pragma unroll
        for (int ktile = 0; ktile < 4; ktile++) {
#pragma unroll
            for (int nt = 0; nt < 8; nt++) {
                uint32_t bb[2];
                bb[0] = smw[KS_W + (nt * 8 + g) * 36 + ktile * 8 + q];
                bb[1] = smw[KS_W + (nt * 8 + g) * 36 + ktile * 8 + q + 4];
                mma_fp16(s[nt], qf[ktile], bb);
            }
        }

        // ---- mask + warp-local online softmax ----
        const int ig0 = qt * 64 + r0 + g;
        const int ig1 = ig0 + 8;
#pragma unroll
        for (int nt = 0; nt < 8; nt++) {
            const int jg = kt * 64 + nt * 8 + 2 * q;
            int d00 = ig0 - jg;     if (d00 < 0 || d00 >= WIN_) s[nt][0] = -1e30f;
            int d01 = ig0 - jg - 1; if (d01 < 0 || d01 >= WIN_) s[nt][1] = -1e30f;
            int d10 = ig1 - jg;     if (d10 < 0 || d10 >= WIN_) s[nt][2] = -1e30f;
            int d11 = ig1 - jg - 1; if (d11 < 0 || d11 >= WIN_) s[nt][3] = -1e30f;
        }
        float mx0 = -1e30f, mx1 = -1e30f;
#pragma unroll
        for (int nt = 0; nt < 8; nt++) {
            mx0 = fmaxf(mx0, fmaxf(s[nt][0], s[nt][1]));
            mx1 = fmaxf(mx1, fmaxf(s[nt][2], s[nt][3]));
        }
        mx0 = fmaxf(mx0, __shfl_xor_sync(0xffffffffu, mx0, 1));
        mx0 = fmaxf(mx0, __shfl_xor_sync(0xffffffffu, mx0, 2));
        mx1 = fmaxf(mx1, __shfl_xor_sync(0xffffffffu, mx1, 1));
        mx1 = fmaxf(mx1, __shfl_xor_sync(0xffffffffu, mx1, 2));

        const float mn0 = fmaxf(m0, mx0), mn1 = fmaxf(m1, mx1);
        const float e0 = __expf(m0 - mn0), e1 = __expf(m1 - mn1);
        float rs0 = 0.f, rs1 = 0.f;

        float pv[8][4];
#pragma unroll
        for (int nt = 0; nt < 8; nt++) {
            pv[nt][0] = __expf(s[nt][0] - mn0);
            pv[nt][1] = __expf(s[nt][1] - mn0);
            pv[nt][2] = __expf(s[nt][2] - mn1);
            pv[nt][3] = __expf(s[nt][3] - mn1);
            rs0 += pv[nt][0] + pv[nt][1];
            rs1 += pv[nt][2] + pv[nt][3];
        }
        uint32_t pf[4][4];
#pragma unroll
        for (int ktile = 0; ktile < 4; ktile++) {
            pf[ktile][0] = pack_h2(pv[2 * ktile][0],     pv[2 * ktile][1]);
            pf[ktile][1] = pack_h2(pv[2 * ktile][2],     pv[2 * ktile][3]);
            pf[ktile][2] = pack_h2(pv[2 * ktile + 1][0], pv[2 * ktile + 1][1]);
            pf[ktile][3] = pack_h2(pv[2 * ktile + 1][2], pv[2 * ktile + 1][3]);
        }
        rs0 += __shfl_xor_sync(0xffffffffu, rs0, 1);
        rs0 += __shfl_xor_sync(0xffffffffu, rs0, 2);
        rs1 += __shfl_xor_sync(0xffffffffu, rs1, 1);
        rs1 += __shfl_xor_sync(0xffffffffu, rs1, 2);

        l0 = l0 * e0 + rs0;  m0 = mn0;
        l1 = l1 * e1 + rs1;  m1 = mn1;

#pragma unroll
        for (int nt = 0; nt < 8; nt++) {
            oc[nt][0] *= e0; oc[nt][1] *= e0;
            oc[nt][2] *= e1; oc[nt][3] *= e1;
        }

        // ---- O += P @ V ----
#pragma unroll
        for (int ktile = 0; ktile < 4; ktile++) {
#pragma unroll
            for (int nt = 0; nt < 8; nt++) {
                uint32_t bb[2];
                bb[0] = smw[VS_W + (ktile * 8 + q    ) * 68 + nt * 8 + g];
                bb[1] = smw[VS_W + (ktile * 8 + q + 4) * 68 + nt * 8 + g];
                mma_fp16(oc[nt], pf[ktile], bb);
            }
        }
    }

    // ---- normalize + write A-fragment-permuted fp16 output ----
    const float inv0 = 1.f / l0, inv1 = 1.f / l1;
    const int mt = (b * T_ + qt * 64 + r0) >> 4;
#pragma unroll
    for (int ktl = 0; ktl < 4; ktl++) {
        uint4 v;
        v.x = pack_h2(oc[2 * ktl][0] * inv0,     oc[2 * ktl][1] * inv0);
        v.y = pack_h2(oc[2 * ktl][2] * inv1,     oc[2 * ktl][3] * inv1);
        v.z = pack_h2(oc[2 * ktl + 1][0] * inv0, oc[2 * ktl + 1][1] * inv0);
        v.w = pack_h2(oc[2 * ktl + 1][2] * inv1, oc[2 * ktl + 1][3] * inv1);
        const size_t chunk = ((size_t)mt * (H_ / 16) + (h * 4 + ktl)) * 32 + lane;
        ((uint4*)outp)[chunk] = v;
    }
}

// ---------------------------------------------------------------------------
// Launch: repack(x, W) -> QKV GEMM (fp16 out) -> attention -> out GEMM
// ---------------------------------------------------------------------------
extern "C" void kernel_launch(void* const* d_in, const int* in_sizes, int n_in,
                              void* d_out, int out_size)
{
    const float* x     = (const float*)d_in[0];
    const float* W_qkv = (const float*)d_in[1];
    const float* b_qkv = (const float*)d_in[2];
    const float* W_out = (const float*)d_in[3];
    const float* b_out = (const float*)d_in[4];
    float* out = (float*)d_out;

    __half* qkv;  cudaGetSymbolAddress((void**)&qkv,  g_qkv);
    __half* xp;   cudaGetSymbolAddress((void**)&xp,   g_xp);
    __half* attp; cudaGetSymbolAddress((void**)&attp, g_attp);
    __half* wqp;  cudaGetSymbolAddress((void**)&wqp,  g_wqkvp);
    __half* wop;  cudaGetSymbolAddress((void**)&wop,  g_woutp);

    const int M = B_ * T_;   // 4096

    // 0) repack + fp16-round operands into fragment order
    {
        const int na = (M / 16) * (H_ / 16) * 32;
        repack_a_fp16<<<(na + 255) / 256, 256>>>(x, xp, M, H_);
        const int nbq = ((3 * H_) / 8) * (H_ / 32) * 32;
        repack_b_fp16<<<(nbq + 255) / 256, 256>>>(W_qkv, wqp, H_, 3 * H_);
        const int nbo = (H_ / 8) * (H_ / 32) * 32;
        repack_b_fp16<<<(nbo + 255) / 256, 256>>>(W_out, wop, H_, H_);
    }

    cudaFuncSetAttribute(gemm_fp16_bias<true>,
                         cudaFuncAttributeMaxDynamicSharedMemorySize, GEMM_SMEM);
    cudaFuncSetAttribute(gemm_fp16_bias<false>,
                         cudaFuncAttributeMaxDynamicSharedMemorySize, GEMM_SMEM);

    // 1) QKV projection: [4096,1024] @ [1024,3072] + bias -> fp16 qkv
    {
        dim3 grid((3 * H_) / BN, M / BM);     // (24, 32)
        gemm_fp16_bias<true><<<grid, 128, GEMM_SMEM>>>(xp, wqp, b_qkv, qkv, M, 3 * H_, H_);
    }

    // 2) Banded attention -> fp16 fragment-permuted output
    {
        cudaFuncSetAttribute(attn_fp16_kernel,
                             cudaFuncAttributeMaxDynamicSharedMemorySize, ATTN_SMEM4);
        dim3 grid(T_ / 64, NH_, B_);
        attn_fp16_kernel<<<grid, 128, ATTN_SMEM4>>>(attp);
    }

    // 3) Output projection: [4096,1024] @ [1024,1024] + bias -> fp32 out
    {
        dim3 grid(H_ / BN, M / BM);           // (8, 32)
        gemm_fp16_bias<false><<<grid, 128, GEMM_SMEM>>>(attp, wop, b_out, out, M, H_, H_);
    }
}